// round 11
// baseline (speedup 1.0000x reference)
#include <cuda_runtime.h>
#include <cuda_bf16.h>
#include <mma.h>
#include <cstdint>

using namespace nvcuda;

// ---------------------------------------------------------------------------
// Problem constants
// ---------------------------------------------------------------------------
constexpr int NN   = 16384;     // total nodes
constexpr int H    = 256;       // hidden
constexpr int EE   = 131072;    // edges
constexpr int DEG  = 8;
constexpr int BG   = 256;       // graphs
constexpr int NPG  = 64;        // nodes/graph
constexpr int LG   = 4;         // GAT layers

// ---------------------------------------------------------------------------
// Scratch (static device globals; allocation-free)
// ---------------------------------------------------------------------------
__device__ float g_h  [NN * H];
__device__ float g_m  [NN * H];
__device__ float g_qkv[NN * 3 * H];
__device__ float g_edot[LG * EE];
__device__ float g_av[132];
__device__ float g_gsc[NN];
__device__ __nv_bfloat16 g_bth[1 << 20];     // transposed weights, bf16 hi
__device__ __nv_bfloat16 g_btl[1 << 20];     // transposed weights, bf16 lo
__device__ __nv_bfloat16 g_hh [NN * H];      // h split hi
__device__ __nv_bfloat16 g_hl [NN * H];      // h split lo
__device__ __nv_bfloat16 g_ffh[NN * 2 * H];  // ff mid split hi
__device__ __nv_bfloat16 g_ffl[NN * 2 * H];  // ff mid split lo
__device__ __nv_bfloat16 g_nfh[NN * 64];     // node_feats split hi
__device__ __nv_bfloat16 g_nfl[NN * 64];     // node_feats split lo

// ---------------------------------------------------------------------------
// Helpers
// ---------------------------------------------------------------------------
__device__ __forceinline__ float wredsum(float v) {
    #pragma unroll
    for (int o = 16; o > 0; o >>= 1) v += __shfl_xor_sync(0xffffffffu, v, o);
    return v;
}

__device__ __forceinline__ void bf16split(float x, __nv_bfloat16& hi, __nv_bfloat16& lo) {
    hi = __float2bfloat16(x);
    lo = __float2bfloat16(x - __bfloat162float(hi));
}

// ---------------------------------------------------------------------------
// Weight preprocessing: transpose [K,N] -> [N,K], split fp32 -> bf16 hi/lo
// ---------------------------------------------------------------------------
struct WDesc { const float* src; int K; int N; int off; };
struct WTab  { WDesc w[11]; };

__global__ __launch_bounds__(256) void prep_kernel(WTab tab, int total) {
    int idx = blockIdx.x * 256 + threadIdx.x;
    if (idx >= total) return;
    int acc = 0;
    #pragma unroll
    for (int i = 0; i < 11; i++) {
        int K = tab.w[i].K, Nn = tab.w[i].N;
        int sz = K * Nn;
        if (idx < acc + sz) {
            int r = idx - acc;            // src-linear: r = k*N + n
            int k = r / Nn, n = r % Nn;
            __nv_bfloat16 hi, lo;
            bf16split(tab.w[i].src[r], hi, lo);
            int d = tab.w[i].off + n * K + k;
            g_bth[d] = hi;
            g_btl[d] = lo;
            return;
        }
        acc += sz;
    }
}

// node_feats fp32 -> bf16 hi/lo (same layout)
__global__ __launch_bounds__(256) void nfsplit_kernel(const float* __restrict__ nf) {
    int i = blockIdx.x * 256 + threadIdx.x;
    __nv_bfloat16 hi, lo;
    bf16split(nf[i], hi, lo);
    g_nfh[i] = hi;
    g_nfl[i] = lo;
}

// ---------------------------------------------------------------------------
// bf16-split tensor-core GEMM, register-staged double buffer (R6 structure).
// C[16384 x ndim] = A[16384 x KDIM] @ W (+bias)(+act)
// A pre-split (Ah_g/Al_g bf16), B = W^T split (Bth/Btl bf16 [ndim][KDIM]).
// CTA tile 128x128, 8 warps (32x64), BK=32, WMMA m16n16k16, 3-term product.
// EPI: 0 none, 1 gelu, 2 relu.  OUTM: bit0 = write fp32 C, bit1 = write split C.
// ---------------------------------------------------------------------------
constexpr int LK = 48;                       // SMEM row stride (bf16 elems)
constexpr int TILE_E = 128 * LK;             // elems per operand tile
constexpr int STAGE_E = 4 * TILE_E;          // Ah, Al, Bh, Bl
constexpr int GEMM_SMEM_BYTES = 2 * STAGE_E * 2;  // 98304

template<int KDIM, int EPI, int OUTM>
__global__ __launch_bounds__(256) void tgemm(const __nv_bfloat16* __restrict__ Ah_g,
                                             const __nv_bfloat16* __restrict__ Al_g,
                                             const __nv_bfloat16* __restrict__ Bth,
                                             const __nv_bfloat16* __restrict__ Btl,
                                             const float* __restrict__ bias,
                                             float* __restrict__ Cf,
                                             __nv_bfloat16* __restrict__ Ch,
                                             __nv_bfloat16* __restrict__ Cl,
                                             int ndim) {
    extern __shared__ char smem_raw[];
    __nv_bfloat16* sb = (__nv_bfloat16*)smem_raw;
    __shared__ float s_bias[128];

    const int tid = threadIdx.x, wid = tid >> 5;
    const int bm = blockIdx.y * 128, bn = blockIdx.x * 128;
    const int m0 = (wid & 3) * 32, n0 = (wid >> 2) * 64;

    if (tid < 128) s_bias[tid] = bias ? bias[bn + tid] : 0.f;

    // staging map: thread -> (row r0, 32B half k80); each tile needs 2x16B per thread
    const int r0  = tid >> 1;           // 0..127
    const int k80 = (tid & 1) * 16;     // 0 or 16

    uint4 rg[8];
    auto ldg = [&](int c) {
        const __nv_bfloat16* gA_h = Ah_g + (size_t)(bm + r0) * KDIM + c * 32 + k80;
        const __nv_bfloat16* gA_l = Al_g + (size_t)(bm + r0) * KDIM + c * 32 + k80;
        const __nv_bfloat16* gB_h = Bth  + (size_t)(bn + r0) * KDIM + c * 32 + k80;
        const __nv_bfloat16* gB_l = Btl  + (size_t)(bn + r0) * KDIM + c * 32 + k80;
        rg[0] = *(const uint4*)(gA_h);     rg[1] = *(const uint4*)(gA_h + 8);
        rg[2] = *(const uint4*)(gA_l);     rg[3] = *(const uint4*)(gA_l + 8);
        rg[4] = *(const uint4*)(gB_h);     rg[5] = *(const uint4*)(gB_h + 8);
        rg[6] = *(const uint4*)(gB_l);     rg[7] = *(const uint4*)(gB_l + 8);
    };
    auto sts = [&](int s) {
        __nv_bfloat16* base = sb + s * STAGE_E + r0 * LK + k80;
        *(uint4*)(base + 0 * TILE_E)     = rg[0];
        *(uint4*)(base + 0 * TILE_E + 8) = rg[1];
        *(uint4*)(base + 1 * TILE_E)     = rg[2];
        *(uint4*)(base + 1 * TILE_E + 8) = rg[3];
        *(uint4*)(base + 2 * TILE_E)     = rg[4];
        *(uint4*)(base + 2 * TILE_E + 8) = rg[5];
        *(uint4*)(base + 3 * TILE_E)     = rg[6];
        *(uint4*)(base + 3 * TILE_E + 8) = rg[7];
    };

    wmma::fragment<wmma::accumulator, 16, 16, 16, float> acc[2][4];
    #pragma unroll
    for (int m = 0; m < 2; m++)
        #pragma unroll
        for (int n = 0; n < 4; n++) wmma::fill_fragment(acc[m][n], 0.f);

    constexpr int NC = KDIM / 32;
    ldg(0); sts(0);
    __syncthreads();

    for (int c = 0; c < NC; c++) {
        if (c + 1 < NC) ldg(c + 1);
        const __nv_bfloat16* Ah = sb + (c & 1) * STAGE_E;
        const __nv_bfloat16* Al = Ah + TILE_E;
        const __nv_bfloat16* Bh = Ah + 2 * TILE_E;
        const __nv_bfloat16* Bl = Ah + 3 * TILE_E;
        #pragma unroll
        for (int k2 = 0; k2 < 2; k2++) {
            const int kk = k2 * 16;
            wmma::fragment<wmma::matrix_a, 16, 16, 16, __nv_bfloat16, wmma::row_major> ah0, ah1, al0, al1;
            wmma::load_matrix_sync(ah0, Ah + (m0     ) * LK + kk, LK);
            wmma::load_matrix_sync(ah1, Ah + (m0 + 16) * LK + kk, LK);
            wmma::load_matrix_sync(al0, Al + (m0     ) * LK + kk, LK);
            wmma::load_matrix_sync(al1, Al + (m0 + 16) * LK + kk, LK);
            #pragma unroll
            for (int nn = 0; nn < 4; nn++) {
                wmma::fragment<wmma::matrix_b, 16, 16, 16, __nv_bfloat16, wmma::col_major> bh, bl;
                wmma::load_matrix_sync(bh, Bh + (n0 + nn * 16) * LK + kk, LK);
                wmma::load_matrix_sync(bl, Bl + (n0 + nn * 16) * LK + kk, LK);
                wmma::mma_sync(acc[0][nn], ah0, bh, acc[0][nn]);
                wmma::mma_sync(acc[1][nn], ah1, bh, acc[1][nn]);
                wmma::mma_sync(acc[0][nn], ah0, bl, acc[0][nn]);
                wmma::mma_sync(acc[1][nn], ah1, bl, acc[1][nn]);
                wmma::mma_sync(acc[0][nn], al0, bh, acc[0][nn]);
                wmma::mma_sync(acc[1][nn], al1, bh, acc[1][nn]);
            }
        }
        if (c + 1 < NC) sts((c + 1) & 1);
        __syncthreads();
    }

    // epilogue: stage through SMEM, apply bias/act, coalesced stores
    float* Cs = (float*)smem_raw;                 // [128][132]
    #pragma unroll
    for (int m = 0; m < 2; m++)
        #pragma unroll
        for (int n = 0; n < 4; n++)
            wmma::store_matrix_sync(Cs + (m0 + m * 16) * 132 + n0 + n * 16,
                                    acc[m][n], 132, wmma::mem_row_major);
    __syncthreads();

    #pragma unroll
    for (int i = 0; i < 16; i++) {
        int idx4 = tid + i * 256;
        int r = idx4 >> 5, c4 = (idx4 & 31) * 4;
        float4 v = *(float4*)(Cs + r * 132 + c4);
        v.x += s_bias[c4 + 0]; v.y += s_bias[c4 + 1];
        v.z += s_bias[c4 + 2]; v.w += s_bias[c4 + 3];
        if (EPI == 1) {
            v.x = 0.5f * v.x * (1.f + erff(v.x * 0.70710678118654752f));
            v.y = 0.5f * v.y * (1.f + erff(v.y * 0.70710678118654752f));
            v.z = 0.5f * v.z * (1.f + erff(v.z * 0.70710678118654752f));
            v.w = 0.5f * v.w * (1.f + erff(v.w * 0.70710678118654752f));
        } else if (EPI == 2) {
            v.x = fmaxf(v.x, 0.f); v.y = fmaxf(v.y, 0.f);
            v.z = fmaxf(v.z, 0.f); v.w = fmaxf(v.w, 0.f);
        }
        size_t o = (size_t)(bm + r) * ndim + bn + c4;
        if (OUTM & 1) *(float4*)(Cf + o) = v;
        if (OUTM & 2) {
            __nv_bfloat16 h4[4], l4[4];
            bf16split(v.x, h4[0], l4[0]); bf16split(v.y, h4[1], l4[1]);
            bf16split(v.z, h4[2], l4[2]); bf16split(v.w, h4[3], l4[3]);
            *(uint2*)(Ch + o) = *(uint2*)h4;
            *(uint2*)(Cl + o) = *(uint2*)l4;
        }
    }
}

// ---------------------------------------------------------------------------
// av[l][k] = sum_j We[k,j] * gat_a[l, 2H+j] ;  bs[l] = sum_j be[j]*gat_a[l,2H+j]
// ---------------------------------------------------------------------------
__global__ void av_kernel(const float* __restrict__ We, const float* __restrict__ be,
                          const float* __restrict__ gat_a) {
    int t = threadIdx.x;
    if (t < 128) {
        int l = t >> 5, k = t & 31;
        const float* a2e = gat_a + l * 768 + 512;
        float s = 0.f;
        for (int j = 0; j < H; j++) s += We[k * H + j] * a2e[j];
        g_av[t] = s;
    } else if (t < 132) {
        int l = t - 128;
        const float* a2e = gat_a + l * 768 + 512;
        float s = 0.f;
        for (int j = 0; j < H; j++) s += be[j] * a2e[j];
        g_av[128 + l] = s;
    }
}

__global__ __launch_bounds__(256) void edot_kernel(const float* __restrict__ ef) {
    __shared__ float sav[132];
    int t = threadIdx.x;
    if (t < 132) sav[t] = g_av[t];
    __syncthreads();
    int e = blockIdx.x * 256 + t;
    float f[32];
    const float4* p = (const float4*)(ef + (size_t)e * 32);
    #pragma unroll
    for (int i = 0; i < 8; i++) {
        float4 v = p[i];
        f[4*i] = v.x; f[4*i+1] = v.y; f[4*i+2] = v.z; f[4*i+3] = v.w;
    }
    #pragma unroll
    for (int l = 0; l < LG; l++) {
        float s = sav[128 + l];
        #pragma unroll
        for (int k = 0; k < 32; k++) s += f[k] * sav[l * 32 + k];
        g_edot[l * EE + e] = s;
    }
}

// ---------------------------------------------------------------------------
// GAT layer (per-graph CTA), residual+LN in place into g_h (+ bf16 split)
// ---------------------------------------------------------------------------
__global__ __launch_bounds__(256) void gat_kernel(int l,
                                                  const float* __restrict__ gat_a,
                                                  const float* __restrict__ gat_lng,
                                                  const float* __restrict__ gat_lnb,
                                                  const int* __restrict__ dst) {
    extern __shared__ float sm[];
    float* ms = sm;
    float* s1 = sm + NPG * H;
    float* s2 = s1 + NPG;
    const int b = blockIdx.x, tid = threadIdx.x;
    const int w = tid >> 5, lane = tid & 31;

    const float* msrc = g_m + (size_t)b * NPG * H;
    for (int i = tid * 4; i < NPG * H; i += 1024)
        *(float4*)(ms + i) = *(const float4*)(msrc + i);
    __syncthreads();

    const float* a1 = gat_a + l * 768;
    const float* a2 = a1 + H;
    for (int q = 0; q < 8; q++) {
        int nl = w * 8 + q;
        float p1 = 0.f, p2 = 0.f;
        #pragma unroll
        for (int j = 0; j < 8; j++) {
            int d = lane + 32 * j;
            float v = ms[nl * H + d];
            p1 += v * a1[d];
            p2 += v * a2[d];
        }
        p1 = wredsum(p1);
        p2 = wredsum(p2);
        if (lane == 0) { s1[nl] = p1; s2[nl] = p2; }
    }
    __syncthreads();

    const float* ed  = g_edot + (size_t)l * EE;
    const float* lgg = gat_lng + l * H;
    const float* lgb = gat_lnb + l * H;

    for (int q = 0; q < 8; q++) {
        int nl = w * 8 + q;
        int n  = b * NPG + nl;
        int eb = n * DEG;
        float s1v = s1[nl];
        float lgt[8]; int di[8];
        float mx = -1e30f;
        #pragma unroll
        for (int k = 0; k < 8; k++) {
            di[k] = dst[eb + k] - b * NPG;
            float t = s1v + s2[di[k]] + ed[eb + k];
            t = (t >= 0.f) ? t : 0.01f * t;
            lgt[k] = t;
            mx = fmaxf(mx, t);
        }
        float den = 0.f;
        #pragma unroll
        for (int k = 0; k < 8; k++) { lgt[k] = expf(lgt[k] - mx); den += lgt[k]; }
        float inv = 1.f / den;
        #pragma unroll
        for (int k = 0; k < 8; k++) lgt[k] *= inv;

        float r[8]; float ssum = 0.f;
        #pragma unroll
        for (int j = 0; j < 8; j++) {
            int d = lane + 32 * j;
            float acc = 0.f;
            #pragma unroll
            for (int k = 0; k < 8; k++) acc += lgt[k] * ms[di[k] * H + d];
            acc += g_h[(size_t)n * H + d];
            r[j] = acc; ssum += acc;
        }
        ssum = wredsum(ssum);
        float mean = ssum * (1.f / H);
        float vv = 0.f;
        #pragma unroll
        for (int j = 0; j < 8; j++) { float t = r[j] - mean; vv += t * t; }
        vv = wredsum(vv);
        float rstd = rsqrtf(vv * (1.f / H) + 1e-5f);
        #pragma unroll
        for (int j = 0; j < 8; j++) {
            int d = lane + 32 * j;
            float o = (r[j] - mean) * rstd * lgg[d] + lgb[d];
            size_t off = (size_t)n * H + d;
            g_h[off] = o;
            __nv_bfloat16 hh, hl;
            bf16split(o, hh, hl);
            g_hh[off] = hh;
            g_hl[off] = hl;
        }
    }
}

// ---------------------------------------------------------------------------
// Global attention: one CTA per (graph, head); reads fused qkv buffer
// ---------------------------------------------------------------------------
__global__ __launch_bounds__(256) void attn_kernel() {
    const int b = blockIdx.x >> 3, hd = blockIdx.x & 7;
    __shared__ float qs[64][33], ks[64][33], vs[64][33], ps[8][64];
    const int tid = threadIdx.x;
    for (int i = tid; i < 2048; i += 256) {
        int r = i >> 5, c = i & 31;
        size_t off = (size_t)(b * NPG + r) * 768 + hd * 32 + c;
        qs[r][c] = g_qkv[off];
        ks[r][c] = g_qkv[off + 256];
        vs[r][c] = g_qkv[off + 512];
    }
    __syncthreads();
    const int w = tid >> 5, lane = tid & 31;
    const size_t obase = (size_t)b * NPG * H + hd * 32;
    for (int q8 = 0; q8 < 8; q8++) {
        int i = w * 8 + q8;
        float s0 = 0.f, s1 = 0.f;
        #pragma unroll
        for (int d = 0; d < 32; d++) {
            float qd = qs[i][d];
            s0 += qd * ks[lane][d];
            s1 += qd * ks[lane + 32][d];
        }
        s0 *= 0.17677669529663687f;
        s1 *= 0.17677669529663687f;
        float mx = fmaxf(s0, s1);
        #pragma unroll
        for (int o = 16; o > 0; o >>= 1) mx = fmaxf(mx, __shfl_xor_sync(0xffffffffu, mx, o));
        float e0 = expf(s0 - mx), e1 = expf(s1 - mx);
        float sme = wredsum(e0 + e1);
        float inv = 1.f / sme;
        ps[w][lane]      = e0 * inv;
        ps[w][lane + 32] = e1 * inv;
        __syncwarp();
        float o = 0.f;
        #pragma unroll
        for (int j = 0; j < 64; j++) o += ps[w][j] * vs[j][lane];
        g_m[obase + (size_t)i * H + lane] = o;
    }
}

// ---------------------------------------------------------------------------
// x = LayerNorm(x + y), y=g_m, x=g_h  (+ bf16 split of result)
// ---------------------------------------------------------------------------
__global__ __launch_bounds__(256) void resln_kernel(const float* __restrict__ g,
                                                    const float* __restrict__ bt,
                                                    float eps) {
    const int w = threadIdx.x >> 5, lane = threadIdx.x & 31;
    const int n = blockIdx.x * 8 + w;
    float r[8]; float s = 0.f;
    #pragma unroll
    for (int j = 0; j < 8; j++) {
        int d = lane + 32 * j;
        float v = g_h[(size_t)n * H + d] + g_m[(size_t)n * H + d];
        r[j] = v; s += v;
    }
    s = wredsum(s);
    float mean = s * (1.f / H);
    float vv = 0.f;
    #pragma unroll
    for (int j = 0; j < 8; j++) { float t = r[j] - mean; vv += t * t; }
    vv = wredsum(vv);
    float rstd = rsqrtf(vv * (1.f / H) + eps);
    #pragma unroll
    for (int j = 0; j < 8; j++) {
        int d = lane + 32 * j;
        float o = (r[j] - mean) * rstd * g[d] + bt[d];
        size_t off = (size_t)n * H + d;
        g_h[off] = o;
        __nv_bfloat16 hh, hl;
        bf16split(o, hh, hl);
        g_hh[off] = hh;
        g_hl[off] = hl;
    }
}

__global__ __launch_bounds__(256) void gsc_kernel(const float* __restrict__ gW2,
                                                  const float* __restrict__ gb2) {
    const int w = threadIdx.x >> 5, lane = threadIdx.x & 31;
    const int n = blockIdx.x * 8 + w;
    float s = 0.f;
    #pragma unroll
    for (int j = 0; j < 8; j++) {
        int d = lane + 32 * j;
        s += g_m[(size_t)n * H + d] * gW2[d];
    }
    s = wredsum(s);
    if (lane == 0) g_gsc[n] = s + gb2[0];
}

__global__ __launch_bounds__(256) void readout_kernel(float* __restrict__ out) {
    const int b = blockIdx.x, tid = threadIdx.x;
    __shared__ float sg[64], pe[64];
    if (tid < 64) sg[tid] = g_gsc[b * NPG + tid];
    __syncthreads();
    if (tid < 64) {
        float mx = -1e30f;
        for (int n = 0; n < 64; n++) mx = fmaxf(mx, sg[n]);
        float se = 0.f;
        for (int n = 0; n < 64; n++) se += expf(sg[n] - mx);
        pe[tid] = expf(sg[tid] - mx) / se;
    }
    __syncthreads();
    float acc = 0.f;
    for (int n = 0; n < 64; n++)
        acc += pe[n] * g_h[(size_t)(b * NPG + n) * H + tid];
    out[b * H + tid] = acc;
}

// ---------------------------------------------------------------------------
// Launch
// ---------------------------------------------------------------------------
extern "C" void kernel_launch(void* const* d_in, const int* in_sizes, int n_in,
                              void* d_out, int out_size) {
    const float* node_feats = (const float*)d_in[0];
    const float* edge_feats = (const float*)d_in[1];
    const int*   dst        = (const int*)  d_in[3];
    const float* Wn      = (const float*)d_in[4];
    const float* bn      = (const float*)d_in[5];
    const float* We      = (const float*)d_in[6];
    const float* be      = (const float*)d_in[7];
    const float* gat_W   = (const float*)d_in[8];
    const float* gat_a   = (const float*)d_in[9];
    const float* gat_lng = (const float*)d_in[10];
    const float* gat_lnb = (const float*)d_in[11];
    const float* Wq      = (const float*)d_in[12];
    const float* Wk      = (const float*)d_in[13];
    const float* Wv      = (const float*)d_in[14];
    const float* att_lng = (const float*)d_in[15];
    const float* att_lnb = (const float*)d_in[16];
    const float* ff_W1   = (const float*)d_in[17];
    const float* ff_b1   = (const float*)d_in[18];
    const float* ff_W2   = (const float*)d_in[19];
    const float* ff_b2   = (const float*)d_in[20];
    const float* ff_lng  = (const float*)d_in[21];
    const float* ff_lnb  = (const float*)d_in[22];
    const float* gW1     = (const float*)d_in[23];
    const float* gb1     = (const float*)d_in[24];
    const float* gW2     = (const float*)d_in[25];
    const float* gb2     = (const float*)d_in[26];
    float* out = (float*)d_out;

    float *ph, *pm, *pqkv;
    __nv_bfloat16 *pwh, *pwl, *phh, *phl, *pffh, *pffl, *pnfh, *pnfl;
    cudaGetSymbolAddress((void**)&ph,   g_h);
    cudaGetSymbolAddress((void**)&pm,   g_m);
    cudaGetSymbolAddress((void**)&pqkv, g_qkv);
    cudaGetSymbolAddress((void**)&pwh,  g_bth);
    cudaGetSymbolAddress((void**)&pwl,  g_btl);
    cudaGetSymbolAddress((void**)&phh,  g_hh);
    cudaGetSymbolAddress((void**)&phl,  g_hl);
    cudaGetSymbolAddress((void**)&pffh, g_ffh);
    cudaGetSymbolAddress((void**)&pffl, g_ffl);
    cudaGetSymbolAddress((void**)&pnfh, g_nfh);
    cudaGetSymbolAddress((void**)&pnfl, g_nfl);

    // weight offsets in the transposed/split buffers
    const int O_WN = 0;
    const int O_G0 = 16384, O_G1 = 81920, O_G2 = 147456, O_G3 = 212992;
    const int O_QKV = 278528;                 // 3 x 256x256 concatenated along N
    const int O_F1 = 475136;                  // 256x512
    const int O_F2 = 606208;                  // 512x256
    const int O_GW = 737280;                  // 256x256
    WTab tab;
    tab.w[0]  = { Wn,              64,  256, O_WN };
    tab.w[1]  = { gat_W + 0*65536, 256, 256, O_G0 };
    tab.w[2]  = { gat_W + 1*65536, 256, 256, O_G1 };
    tab.w[3]  = { gat_W + 2*65536, 256, 256, O_G2 };
    tab.w[4]  = { gat_W + 3*65536, 256, 256, O_G3 };
    tab.w[5]  = { Wq,              256, 256, O_QKV };
    tab.w[6]  = { Wk,              256, 256, O_QKV + 65536 };
    tab.w[7]  = { Wv,              256, 256, O_QKV + 131072 };
    tab.w[8]  = { ff_W1,           256, 512, O_F1 };
    tab.w[9]  = { ff_W2,           512, 256, O_F2 };
    tab.w[10] = { gW1,             256, 256, O_GW };
    const int TOTAL_W = 802816;

    cudaFuncSetAttribute(tgemm<64, 0, 3>,  cudaFuncAttributeMaxDynamicSharedMemorySize, GEMM_SMEM_BYTES);
    cudaFuncSetAttribute(tgemm<256, 0, 1>, cudaFuncAttributeMaxDynamicSharedMemorySize, GEMM_SMEM_BYTES);
    cudaFuncSetAttribute(tgemm<256, 1, 2>, cudaFuncAttributeMaxDynamicSharedMemorySize, GEMM_SMEM_BYTES);
    cudaFuncSetAttribute(tgemm<512, 0, 1>, cudaFuncAttributeMaxDynamicSharedMemorySize, GEMM_SMEM_BYTES);
    cudaFuncSetAttribute(tgemm<256, 2, 1>, cudaFuncAttributeMaxDynamicSharedMemorySize, GEMM_SMEM_BYTES);
    const int GAT_SMEM = (NPG * H + 128) * (int)sizeof(float);
    cudaFuncSetAttribute(gat_kernel, cudaFuncAttributeMaxDynamicSharedMemorySize, GAT_SMEM);

    // preprocess: weights, node_feats split, edge scalars
    prep_kernel<<<(TOTAL_W + 255) / 256, 256>>>(tab, TOTAL_W);
    nfsplit_kernel<<<NN * 64 / 256, 256>>>(node_feats);
    av_kernel<<<1, 160>>>(We, be, gat_a);
    edot_kernel<<<EE / 256, 256>>>(edge_feats);

    // h = node_feats @ Wn + bn   (writes fp32 h + split)
    tgemm<64, 0, 3><<<dim3(2, 128), 256, GEMM_SMEM_BYTES>>>(
        pnfh, pnfl, pwh + O_WN, pwl + O_WN, bn, ph, phh, phl, 256);

    // GAT stack
    const int OG[4] = { O_G0, O_G1, O_G2, O_G3 };
    for (int l = 0; l < LG; l++) {
        tgemm<256, 0, 1><<<dim3(2, 128), 256, GEMM_SMEM_BYTES>>>(
            phh, phl, pwh + OG[l], pwl + OG[l], nullptr, pm, nullptr, nullptr, 256);
        gat_kernel<<<BG, 256, GAT_SMEM>>>(l, gat_a, gat_lng, gat_lnb, dst);
    }

    // global attention (fused QKV)
    tgemm<256, 0, 1><<<dim3(6, 128), 256, GEMM_SMEM_BYTES>>>(
        phh, phl, pwh + O_QKV, pwl + O_QKV, nullptr, pqkv, nullptr, nullptr, 768);
    attn_kernel<<<BG * 8, 256>>>();
    resln_kernel<<<NN / 8, 256>>>(att_lng, att_lnb, 1e-6f);

    // feed-forward
    tgemm<256, 1, 2><<<dim3(4, 128), 256, GEMM_SMEM_BYTES>>>(
        phh, phl, pwh + O_F1, pwl + O_F1, ff_b1, nullptr, pffh, pffl, 512);
    tgemm<512, 0, 1><<<dim3(2, 128), 256, GEMM_SMEM_BYTES>>>(
        pffh, pffl, pwh + O_F2, pwl + O_F2, ff_b2, pm, nullptr, nullptr, 256);
    resln_kernel<<<NN / 8, 256>>>(ff_lng, ff_lnb, 1e-6f);

    // gated readout
    tgemm<256, 2, 1><<<dim3(2, 128), 256, GEMM_SMEM_BYTES>>>(
        phh, phl, pwh + O_GW, pwl + O_GW, gb1, pm, nullptr, nullptr, 256);
    gsc_kernel<<<NN / 8, 256>>>(gW2, gb2);
    readout_kernel<<<BG, 256>>>(out);
}

// round 12
// speedup vs baseline: 1.7648x; 1.7648x over previous
#include <cuda_runtime.h>
#include <cuda_bf16.h>
#include <mma.h>
#include <cstdint>

using namespace nvcuda;

// ---------------------------------------------------------------------------
// Problem constants
// ---------------------------------------------------------------------------
constexpr int NN   = 16384;     // total nodes
constexpr int H    = 256;       // hidden
constexpr int EE   = 131072;    // edges
constexpr int DEG  = 8;
constexpr int BG   = 256;       // graphs
constexpr int NPG  = 64;        // nodes/graph
constexpr int LG   = 4;         // GAT layers

// ---------------------------------------------------------------------------
// Scratch (static device globals; allocation-free)
// Packed split layout: [row][K/32 chunks][hi x32 | lo x32]  (row stride 2*K)
// ---------------------------------------------------------------------------
__device__ float g_h  [NN * H];
__device__ float g_m  [NN * H];
__device__ float g_qkv[NN * 3 * H];
__device__ float g_edot[LG * EE];
__device__ float g_av[132];
__device__ float g_gsc[NN];
__device__ __nv_bfloat16 g_wp [1605632];      // packed split weights
__device__ __nv_bfloat16 g_hp [NN * 2 * H];   // packed split h
__device__ __nv_bfloat16 g_ffp[NN * 4 * H];   // packed split ff mid (K=512)
__device__ __nv_bfloat16 g_nfp[NN * 128];     // packed split node_feats (K=64)

// ---------------------------------------------------------------------------
// Helpers
// ---------------------------------------------------------------------------
__device__ __forceinline__ float wredsum(float v) {
    #pragma unroll
    for (int o = 16; o > 0; o >>= 1) v += __shfl_xor_sync(0xffffffffu, v, o);
    return v;
}

__device__ __forceinline__ void bf16split(float x, __nv_bfloat16& hi, __nv_bfloat16& lo) {
    hi = __float2bfloat16(x);
    lo = __float2bfloat16(x - __bfloat162float(hi));
}

// ---------------------------------------------------------------------------
// Weight preprocessing: transpose [K,N]->[N,K], split, pack per-32 chunk
// ---------------------------------------------------------------------------
struct WDesc { const float* src; int K; int N; int off; };
struct WTab  { WDesc w[11]; };

__global__ __launch_bounds__(256) void prep_kernel(WTab tab, int total) {
    int idx = blockIdx.x * 256 + threadIdx.x;
    if (idx >= total) return;
    int acc = 0;
    #pragma unroll
    for (int i = 0; i < 11; i++) {
        int K = tab.w[i].K, Nn = tab.w[i].N;
        int sz = K * Nn;
        if (idx < acc + sz) {
            int r = idx - acc;            // src-linear: r = k*N + n
            int k = r / Nn, n = r % Nn;
            __nv_bfloat16 hi, lo;
            bf16split(tab.w[i].src[r], hi, lo);
            int d = tab.w[i].off + n * 2 * K + (k >> 5) * 64 + (k & 31);
            g_wp[d]      = hi;
            g_wp[d + 32] = lo;
            return;
        }
        acc += sz;
    }
}

// node_feats fp32 -> packed split (K=64, row stride 128)
__global__ __launch_bounds__(256) void nfsplit_kernel(const float* __restrict__ nf) {
    int i = blockIdx.x * 256 + threadIdx.x;     // i = m*64 + k
    int m = i >> 6, k = i & 63;
    __nv_bfloat16 hi, lo;
    bf16split(nf[i], hi, lo);
    int d = m * 128 + (k >> 5) * 64 + (k & 31);
    g_nfp[d]      = hi;
    g_nfp[d + 32] = lo;
}

// ---------------------------------------------------------------------------
// bf16-split tensor-core GEMM, register-staged double buffer (R6 structure),
// packed-split operands (128B contiguous per row-chunk -> 4 full lines/warp).
// C[16384 x ndim] = A[16384 x KDIM] @ W (+bias)(+act)
// EPI: 0 none, 1 gelu, 2 relu.  OUTM: bit0 = fp32 C, bit1 = packed split C.
// ---------------------------------------------------------------------------
constexpr int LK = 48;                        // SMEM row stride (bf16 elems)
constexpr int TILE_P = 128 * LK + 8;          // tile stride (+8 elem skew)
constexpr int STAGE_E = 4 * TILE_P;           // Ah, Al, Bh, Bl
constexpr int GEMM_SMEM_BYTES = 2 * STAGE_E * 2;  // ~98.4KB

template<int KDIM, int EPI, int OUTM>
__global__ __launch_bounds__(256) void tgemm(const __nv_bfloat16* __restrict__ Ap,
                                             const __nv_bfloat16* __restrict__ Bp,
                                             const float* __restrict__ bias,
                                             float* __restrict__ Cf,
                                             __nv_bfloat16* __restrict__ Cpk,
                                             int ndim) {
    extern __shared__ char smem_raw[];
    __nv_bfloat16* sb = (__nv_bfloat16*)smem_raw;
    __shared__ float s_bias[128];

    const int tid = threadIdx.x, wid = tid >> 5;
    const int bm = blockIdx.y * 128, bn = blockIdx.x * 128;
    const int m0 = (wid & 3) * 32, n0 = (wid >> 2) * 64;

    if (tid < 128) s_bias[tid] = bias ? bias[bn + tid] : 0.f;

    // staging map: 8 threads per row-chunk (128B), 4 row-iterations per operand
    const int r0 = tid >> 3;                  // 0..31
    const int kc = (tid & 7) * 8;             // 0..56 within packed 64-group
    const int selA = (kc < 32) ? 0 : TILE_P;  // hi tile or lo tile
    const int col = kc & 31;                  // 0..24

    constexpr int RS = 2 * KDIM;              // packed row stride (elems)

    uint4 rg[8];
    auto ldg = [&](int c) {
        const __nv_bfloat16* gA = Ap + (size_t)(bm + r0) * RS + c * 64 + kc;
        const __nv_bfloat16* gB = Bp + (size_t)(bn + r0) * RS + c * 64 + kc;
        #pragma unroll
        for (int i = 0; i < 4; i++) rg[i]     = *(const uint4*)(gA + (size_t)i * 32 * RS);
        #pragma unroll
        for (int i = 0; i < 4; i++) rg[4 + i] = *(const uint4*)(gB + (size_t)i * 32 * RS);
    };
    auto sts = [&](int s) {
        __nv_bfloat16* ba = sb + s * STAGE_E + selA + col;
        #pragma unroll
        for (int i = 0; i < 4; i++)
            *(uint4*)(ba + (r0 + i * 32) * LK) = rg[i];
        __nv_bfloat16* bb = ba + 2 * TILE_P;
        #pragma unroll
        for (int i = 0; i < 4; i++)
            *(uint4*)(bb + (r0 + i * 32) * LK) = rg[4 + i];
    };

    wmma::fragment<wmma::accumulator, 16, 16, 16, float> acc[2][4];
    #pragma unroll
    for (int m = 0; m < 2; m++)
        #pragma unroll
        for (int n = 0; n < 4; n++) wmma::fill_fragment(acc[m][n], 0.f);

    constexpr int NC = KDIM / 32;
    ldg(0); sts(0);
    __syncthreads();

    for (int c = 0; c < NC; c++) {
        if (c + 1 < NC) ldg(c + 1);
        const __nv_bfloat16* Ah = sb + (c & 1) * STAGE_E;
        const __nv_bfloat16* Al = Ah + TILE_P;
        const __nv_bfloat16* Bh = Ah + 2 * TILE_P;
        const __nv_bfloat16* Bl = Ah + 3 * TILE_P;
        #pragma unroll
        for (int k2 = 0; k2 < 2; k2++) {
            const int kk = k2 * 16;
            wmma::fragment<wmma::matrix_a, 16, 16, 16, __nv_bfloat16, wmma::row_major> ah0, ah1, al0, al1;
            wmma::load_matrix_sync(ah0, Ah + (m0     ) * LK + kk, LK);
            wmma::load_matrix_sync(ah1, Ah + (m0 + 16) * LK + kk, LK);
            wmma::load_matrix_sync(al0, Al + (m0     ) * LK + kk, LK);
            wmma::load_matrix_sync(al1, Al + (m0 + 16) * LK + kk, LK);
            #pragma unroll
            for (int nn = 0; nn < 4; nn++) {
                wmma::fragment<wmma::matrix_b, 16, 16, 16, __nv_bfloat16, wmma::col_major> bh, bl;
                wmma::load_matrix_sync(bh, Bh + (n0 + nn * 16) * LK + kk, LK);
                wmma::load_matrix_sync(bl, Bl + (n0 + nn * 16) * LK + kk, LK);
                wmma::mma_sync(acc[0][nn], ah0, bh, acc[0][nn]);
                wmma::mma_sync(acc[1][nn], ah1, bh, acc[1][nn]);
                wmma::mma_sync(acc[0][nn], ah0, bl, acc[0][nn]);
                wmma::mma_sync(acc[1][nn], ah1, bl, acc[1][nn]);
                wmma::mma_sync(acc[0][nn], al0, bh, acc[0][nn]);
                wmma::mma_sync(acc[1][nn], al1, bh, acc[1][nn]);
            }
        }
        if (c + 1 < NC) sts((c + 1) & 1);
        __syncthreads();
    }

    // epilogue: stage through SMEM, apply bias/act, coalesced stores
    float* Cs = (float*)smem_raw;                 // [128][132]
    #pragma unroll
    for (int m = 0; m < 2; m++)
        #pragma unroll
        for (int n = 0; n < 4; n++)
            wmma::store_matrix_sync(Cs + (m0 + m * 16) * 132 + n0 + n * 16,
                                    acc[m][n], 132, wmma::mem_row_major);
    __syncthreads();

    #pragma unroll
    for (int i = 0; i < 16; i++) {
        int idx4 = tid + i * 256;
        int r = idx4 >> 5, c4 = (idx4 & 31) * 4;
        float4 v = *(float4*)(Cs + r * 132 + c4);
        v.x += s_bias[c4 + 0]; v.y += s_bias[c4 + 1];
        v.z += s_bias[c4 + 2]; v.w += s_bias[c4 + 3];
        if (EPI == 1) {
            v.x = 0.5f * v.x * (1.f + erff(v.x * 0.70710678118654752f));
            v.y = 0.5f * v.y * (1.f + erff(v.y * 0.70710678118654752f));
            v.z = 0.5f * v.z * (1.f + erff(v.z * 0.70710678118654752f));
            v.w = 0.5f * v.w * (1.f + erff(v.w * 0.70710678118654752f));
        } else if (EPI == 2) {
            v.x = fmaxf(v.x, 0.f); v.y = fmaxf(v.y, 0.f);
            v.z = fmaxf(v.z, 0.f); v.w = fmaxf(v.w, 0.f);
        }
        if (OUTM & 1) {
            size_t o = (size_t)(bm + r) * ndim + bn + c4;
            *(float4*)(Cf + o) = v;
        }
        if (OUTM & 2) {
            int gc = bn + c4;
            size_t pb = (size_t)(bm + r) * 2 * ndim + (size_t)(gc >> 5) * 64 + (gc & 31);
            __nv_bfloat16 h4[4], l4[4];
            bf16split(v.x, h4[0], l4[0]); bf16split(v.y, h4[1], l4[1]);
            bf16split(v.z, h4[2], l4[2]); bf16split(v.w, h4[3], l4[3]);
            *(uint2*)(Cpk + pb)      = *(uint2*)h4;
            *(uint2*)(Cpk + pb + 32) = *(uint2*)l4;
        }
    }
}

// ---------------------------------------------------------------------------
// av[l][k] = sum_j We[k,j] * gat_a[l, 2H+j] ;  bs[l] = sum_j be[j]*gat_a[l,2H+j]
// ---------------------------------------------------------------------------
__global__ void av_kernel(const float* __restrict__ We, const float* __restrict__ be,
                          const float* __restrict__ gat_a) {
    int t = threadIdx.x;
    if (t < 128) {
        int l = t >> 5, k = t & 31;
        const float* a2e = gat_a + l * 768 + 512;
        float s = 0.f;
        for (int j = 0; j < H; j++) s += We[k * H + j] * a2e[j];
        g_av[t] = s;
    } else if (t < 132) {
        int l = t - 128;
        const float* a2e = gat_a + l * 768 + 512;
        float s = 0.f;
        for (int j = 0; j < H; j++) s += be[j] * a2e[j];
        g_av[128 + l] = s;
    }
}

__global__ __launch_bounds__(256) void edot_kernel(const float* __restrict__ ef) {
    __shared__ float sav[132];
    int t = threadIdx.x;
    if (t < 132) sav[t] = g_av[t];
    __syncthreads();
    int e = blockIdx.x * 256 + t;
    float f[32];
    const float4* p = (const float4*)(ef + (size_t)e * 32);
    #pragma unroll
    for (int i = 0; i < 8; i++) {
        float4 v = p[i];
        f[4*i] = v.x; f[4*i+1] = v.y; f[4*i+2] = v.z; f[4*i+3] = v.w;
    }
    #pragma unroll
    for (int l = 0; l < LG; l++) {
        float s = sav[128 + l];
        #pragma unroll
        for (int k = 0; k < 32; k++) s += f[k] * sav[l * 32 + k];
        g_edot[l * EE + e] = s;
    }
}

// ---------------------------------------------------------------------------
// GAT layer (per-graph CTA), residual+LN in place into g_h (+ packed split)
// ---------------------------------------------------------------------------
__global__ __launch_bounds__(256) void gat_kernel(int l,
                                                  const float* __restrict__ gat_a,
                                                  const float* __restrict__ gat_lng,
                                                  const float* __restrict__ gat_lnb,
                                                  const int* __restrict__ dst) {
    extern __shared__ float sm[];
    float* ms = sm;
    float* s1 = sm + NPG * H;
    float* s2 = s1 + NPG;
    const int b = blockIdx.x, tid = threadIdx.x;
    const int w = tid >> 5, lane = tid & 31;

    const float* msrc = g_m + (size_t)b * NPG * H;
    for (int i = tid * 4; i < NPG * H; i += 1024)
        *(float4*)(ms + i) = *(const float4*)(msrc + i);
    __syncthreads();

    const float* a1 = gat_a + l * 768;
    const float* a2 = a1 + H;
    for (int q = 0; q < 8; q++) {
        int nl = w * 8 + q;
        float p1 = 0.f, p2 = 0.f;
        #pragma unroll
        for (int j = 0; j < 8; j++) {
            int d = lane + 32 * j;
            float v = ms[nl * H + d];
            p1 += v * a1[d];
            p2 += v * a2[d];
        }
        p1 = wredsum(p1);
        p2 = wredsum(p2);
        if (lane == 0) { s1[nl] = p1; s2[nl] = p2; }
    }
    __syncthreads();

    const float* ed  = g_edot + (size_t)l * EE;
    const float* lgg = gat_lng + l * H;
    const float* lgb = gat_lnb + l * H;

    for (int q = 0; q < 8; q++) {
        int nl = w * 8 + q;
        int n  = b * NPG + nl;
        int eb = n * DEG;
        float s1v = s1[nl];
        float lgt[8]; int di[8];
        float mx = -1e30f;
        #pragma unroll
        for (int k = 0; k < 8; k++) {
            di[k] = dst[eb + k] - b * NPG;
            float t = s1v + s2[di[k]] + ed[eb + k];
            t = (t >= 0.f) ? t : 0.01f * t;
            lgt[k] = t;
            mx = fmaxf(mx, t);
        }
        float den = 0.f;
        #pragma unroll
        for (int k = 0; k < 8; k++) { lgt[k] = expf(lgt[k] - mx); den += lgt[k]; }
        float inv = 1.f / den;
        #pragma unroll
        for (int k = 0; k < 8; k++) lgt[k] *= inv;

        float r[8]; float ssum = 0.f;
        #pragma unroll
        for (int j = 0; j < 8; j++) {
            int d = lane + 32 * j;
            float acc = 0.f;
            #pragma unroll
            for (int k = 0; k < 8; k++) acc += lgt[k] * ms[di[k] * H + d];
            acc += g_h[(size_t)n * H + d];
            r[j] = acc; ssum += acc;
        }
        ssum = wredsum(ssum);
        float mean = ssum * (1.f / H);
        float vv = 0.f;
        #pragma unroll
        for (int j = 0; j < 8; j++) { float t = r[j] - mean; vv += t * t; }
        vv = wredsum(vv);
        float rstd = rsqrtf(vv * (1.f / H) + 1e-5f);
        #pragma unroll
        for (int j = 0; j < 8; j++) {
            int d = lane + 32 * j;
            float o = (r[j] - mean) * rstd * lgg[d] + lgb[d];
            g_h[(size_t)n * H + d] = o;
            __nv_bfloat16 hh, hl;
            bf16split(o, hh, hl);
            size_t pb = (size_t)n * 512 + j * 64 + lane;   // packed: chunk j, elem lane
            g_hp[pb]      = hh;
            g_hp[pb + 32] = hl;
        }
    }
}

// ---------------------------------------------------------------------------
// Global attention: one CTA per (graph, head); reads fused qkv buffer
// ---------------------------------------------------------------------------
__global__ __launch_bounds__(256) void attn_kernel() {
    const int b = blockIdx.x >> 3, hd = blockIdx.x & 7;
    __shared__ float qs[64][33], ks[64][33], vs[64][33], ps[8][64];
    const int tid = threadIdx.x;
    for (int i = tid; i < 2048; i += 256) {
        int r = i >> 5, c = i & 31;
        size_t off = (size_t)(b * NPG + r) * 768 + hd * 32 + c;
        qs[r][c] = g_qkv[off];
        ks[r][c] = g_qkv[off + 256];
        vs[r][c] = g_qkv[off + 512];
    }
    __syncthreads();
    const int w = tid >> 5, lane = tid & 31;
    const size_t obase = (size_t)b * NPG * H + hd * 32;
    for (int q8 = 0; q8 < 8; q8++) {
        int i = w * 8 + q8;
        float s0 = 0.f, s1 = 0.f;
        #pragma unroll
        for (int d = 0; d < 32; d++) {
            float qd = qs[i][d];
            s0 += qd * ks[lane][d];
            s1 += qd * ks[lane + 32][d];
        }
        s0 *= 0.17677669529663687f;
        s1 *= 0.17677669529663687f;
        float mx = fmaxf(s0, s1);
        #pragma unroll
        for (int o = 16; o > 0; o >>= 1) mx = fmaxf(mx, __shfl_xor_sync(0xffffffffu, mx, o));
        float e0 = expf(s0 - mx), e1 = expf(s1 - mx);
        float sme = wredsum(e0 + e1);
        float inv = 1.f / sme;
        ps[w][lane]      = e0 * inv;
        ps[w][lane + 32] = e1 * inv;
        __syncwarp();
        float o = 0.f;
        #pragma unroll
        for (int j = 0; j < 64; j++) o += ps[w][j] * vs[j][lane];
        g_m[obase + (size_t)i * H + lane] = o;
    }
}

// ---------------------------------------------------------------------------
// x = LayerNorm(x + y), y=g_m, x=g_h  (+ packed split of result)
// ---------------------------------------------------------------------------
__global__ __launch_bounds__(256) void resln_kernel(const float* __restrict__ g,
                                                    const float* __restrict__ bt,
                                                    float eps) {
    const int w = threadIdx.x >> 5, lane = threadIdx.x & 31;
    const int n = blockIdx.x * 8 + w;
    float r[8]; float s = 0.f;
    #pragma unroll
    for (int j = 0; j < 8; j++) {
        int d = lane + 32 * j;
        float v = g_h[(size_t)n * H + d] + g_m[(size_t)n * H + d];
        r[j] = v; s += v;
    }
    s = wredsum(s);
    float mean = s * (1.f / H);
    float vv = 0.f;
    #pragma unroll
    for (int j = 0; j < 8; j++) { float t = r[j] - mean; vv += t * t; }
    vv = wredsum(vv);
    float rstd = rsqrtf(vv * (1.f / H) + eps);
    #pragma unroll
    for (int j = 0; j < 8; j++) {
        int d = lane + 32 * j;
        float o = (r[j] - mean) * rstd * g[d] + bt[d];
        g_h[(size_t)n * H + d] = o;
        __nv_bfloat16 hh, hl;
        bf16split(o, hh, hl);
        size_t pb = (size_t)n * 512 + j * 64 + lane;
        g_hp[pb]      = hh;
        g_hp[pb + 32] = hl;
    }
}

__global__ __launch_bounds__(256) void gsc_kernel(const float* __restrict__ gW2,
                                                  const float* __restrict__ gb2) {
    const int w = threadIdx.x >> 5, lane = threadIdx.x & 31;
    const int n = blockIdx.x * 8 + w;
    float s = 0.f;
    #pragma unroll
    for (int j = 0; j < 8; j++) {
        int d = lane + 32 * j;
        s += g_m[(size_t)n * H + d] * gW2[d];
    }
    s = wredsum(s);
    if (lane == 0) g_gsc[n] = s + gb2[0];
}

__global__ __launch_bounds__(256) void readout_kernel(float* __restrict__ out) {
    const int b = blockIdx.x, tid = threadIdx.x;
    __shared__ float sg[64], pe[64];
    if (tid < 64) sg[tid] = g_gsc[b * NPG + tid];
    __syncthreads();
    if (tid < 64) {
        float mx = -1e30f;
        for (int n = 0; n < 64; n++) mx = fmaxf(mx, sg[n]);
        float se = 0.f;
        for (int n = 0; n < 64; n++) se += expf(sg[n] - mx);
        pe[tid] = expf(sg[tid] - mx) / se;
    }
    __syncthreads();
    float acc = 0.f;
    for (int n = 0; n < 64; n++)
        acc += pe[n] * g_h[(size_t)(b * NPG + n) * H + tid];
    out[b * H + tid] = acc;
}

// ---------------------------------------------------------------------------
// Launch
// ---------------------------------------------------------------------------
extern "C" void kernel_launch(void* const* d_in, const int* in_sizes, int n_in,
                              void* d_out, int out_size) {
    const float* node_feats = (const float*)d_in[0];
    const float* edge_feats = (const float*)d_in[1];
    const int*   dst        = (const int*)  d_in[3];
    const float* Wn      = (const float*)d_in[4];
    const float* bn      = (const float*)d_in[5];
    const float* We      = (const float*)d_in[6];
    const float* be      = (const float*)d_in[7];
    const float* gat_W   = (const float*)d_in[8];
    const float* gat_a   = (const float*)d_in[9];
    const float* gat_lng = (const float*)d_in[10];
    const float* gat_lnb = (const float*)d_in[11];
    const float* Wq      = (const float*)d_in[12];
    const float* Wk      = (const float*)d_in[13];
    const float* Wv      = (const float*)d_in[14];
    const float* att_lng = (const float*)d_in[15];
    const float* att_lnb = (const float*)d_in[16];
    const float* ff_W1   = (const float*)d_in[17];
    const float* ff_b1   = (const float*)d_in[18];
    const float* ff_W2   = (const float*)d_in[19];
    const float* ff_b2   = (const float*)d_in[20];
    const float* ff_lng  = (const float*)d_in[21];
    const float* ff_lnb  = (const float*)d_in[22];
    const float* gW1     = (const float*)d_in[23];
    const float* gb1     = (const float*)d_in[24];
    const float* gW2     = (const float*)d_in[25];
    const float* gb2     = (const float*)d_in[26];
    float* out = (float*)d_out;

    float *ph, *pm, *pqkv;
    __nv_bfloat16 *pw, *php, *pffp, *pnfp;
    cudaGetSymbolAddress((void**)&ph,   g_h);
    cudaGetSymbolAddress((void**)&pm,   g_m);
    cudaGetSymbolAddress((void**)&pqkv, g_qkv);
    cudaGetSymbolAddress((void**)&pw,   g_wp);
    cudaGetSymbolAddress((void**)&php,  g_hp);
    cudaGetSymbolAddress((void**)&pffp, g_ffp);
    cudaGetSymbolAddress((void**)&pnfp, g_nfp);

    // packed weight offsets (elems, each weight = 2*K*N)
    const int O_WN  = 0;          // 2*64*256   = 32768
    const int O_G0  = 32768;      // 131072 each
    const int O_G1  = 163840;
    const int O_G2  = 294912;
    const int O_G3  = 425984;
    const int O_QKV = 557056;     // Wq, then Wk +131072, Wv +262144 (contig rows)
    const int O_F1  = 950272;     // 2*256*512 = 262144
    const int O_F2  = 1212416;    // 2*512*256 = 262144
    const int O_GW  = 1474560;    // 131072
    WTab tab;
    tab.w[0]  = { Wn,              64,  256, O_WN };
    tab.w[1]  = { gat_W + 0*65536, 256, 256, O_G0 };
    tab.w[2]  = { gat_W + 1*65536, 256, 256, O_G1 };
    tab.w[3]  = { gat_W + 2*65536, 256, 256, O_G2 };
    tab.w[4]  = { gat_W + 3*65536, 256, 256, O_G3 };
    tab.w[5]  = { Wq,              256, 256, O_QKV };
    tab.w[6]  = { Wk,              256, 256, O_QKV + 131072 };
    tab.w[7]  = { Wv,              256, 256, O_QKV + 262144 };
    tab.w[8]  = { ff_W1,           256, 512, O_F1 };
    tab.w[9]  = { ff_W2,           512, 256, O_F2 };
    tab.w[10] = { gW1,             256, 256, O_GW };
    const int TOTAL_W = 802816;

    cudaFuncSetAttribute(tgemm<64, 0, 3>,  cudaFuncAttributeMaxDynamicSharedMemorySize, GEMM_SMEM_BYTES);
    cudaFuncSetAttribute(tgemm<256, 0, 1>, cudaFuncAttributeMaxDynamicSharedMemorySize, GEMM_SMEM_BYTES);
    cudaFuncSetAttribute(tgemm<256, 1, 2>, cudaFuncAttributeMaxDynamicSharedMemorySize, GEMM_SMEM_BYTES);
    cudaFuncSetAttribute(tgemm<512, 0, 1>, cudaFuncAttributeMaxDynamicSharedMemorySize, GEMM_SMEM_BYTES);
    cudaFuncSetAttribute(tgemm<256, 2, 1>, cudaFuncAttributeMaxDynamicSharedMemorySize, GEMM_SMEM_BYTES);
    const int GAT_SMEM = (NPG * H + 128) * (int)sizeof(float);
    cudaFuncSetAttribute(gat_kernel, cudaFuncAttributeMaxDynamicSharedMemorySize, GAT_SMEM);

    // preprocess: weights, node_feats split, edge scalars
    prep_kernel<<<(TOTAL_W + 255) / 256, 256>>>(tab, TOTAL_W);
    nfsplit_kernel<<<NN * 64 / 256, 256>>>(node_feats);
    av_kernel<<<1, 160>>>(We, be, gat_a);
    edot_kernel<<<EE / 256, 256>>>(edge_feats);

    // h = node_feats @ Wn + bn   (writes fp32 h + packed split)
    tgemm<64, 0, 3><<<dim3(2, 128), 256, GEMM_SMEM_BYTES>>>(
        pnfp, pw + O_WN, bn, ph, php, 256);

    // GAT stack
    const int OG[4] = { O_G0, O_G1, O_G2, O_G3 };
    for (int l = 0; l < LG; l++) {
        tgemm<256, 0, 1><<<dim3(2, 128), 256, GEMM_SMEM_BYTES>>>(
            php, pw + OG[l], nullptr, pm, nullptr, 256);
        gat_kernel<<<BG, 256, GAT_SMEM>>>(l, gat_a, gat_lng, gat_lnb, dst);
    }

    // global attention (fused QKV)
    tgemm<256, 0, 1><<<dim3(6, 128), 256, GEMM_SMEM_BYTES>>>(
        php, pw + O_QKV, nullptr, pqkv, nullptr, 768);
    attn_kernel<<<BG * 8, 256>>>();
    resln_kernel<<<NN / 8, 256>>>(att_lng, att_lnb, 1e-6f);

    // feed-forward
    tgemm<256, 1, 2><<<dim3(4, 128), 256, GEMM_SMEM_BYTES>>>(
        php, pw + O_F1, ff_b1, nullptr, pffp, 512);
    tgemm<512, 0, 1><<<dim3(2, 128), 256, GEMM_SMEM_BYTES>>>(
        pffp, pw + O_F2, ff_b2, pm, nullptr, 256);
    resln_kernel<<<NN / 8, 256>>>(ff_lng, ff_lnb, 1e-6f);

    // gated readout
    tgemm<256, 2, 1><<<dim3(2, 128), 256, GEMM_SMEM_BYTES>>>(
        php, pw + O_GW, gb1, pm, nullptr, 256);
    gsc_kernel<<<NN / 8, 256>>>(gW2, gb2);
    readout_kernel<<<BG, 256>>>(out);
}

// round 15
// speedup vs baseline: 1.8151x; 1.0285x over previous
#include <cuda_runtime.h>
#include <cuda_bf16.h>
#include <mma.h>
#include <cstdint>

using namespace nvcuda;

// ---------------------------------------------------------------------------
// Problem constants
// ---------------------------------------------------------------------------
constexpr int NN   = 16384;     // total nodes
constexpr int H    = 256;       // hidden
constexpr int EE   = 131072;    // edges
constexpr int DEG  = 8;
constexpr int BG   = 256;       // graphs
constexpr int NPG  = 64;        // nodes/graph
constexpr int LG   = 4;         // GAT layers

// ---------------------------------------------------------------------------
// Scratch (static device globals; allocation-free)
// Packed split layout: [row][K/32 chunks][hi x32 | lo x32]  (row stride 2*K)
// ---------------------------------------------------------------------------
__device__ float g_h  [NN * H];
__device__ float g_m  [NN * H];
__device__ float g_qkv[NN * 3 * H];
__device__ float g_edot[LG * EE];
__device__ float g_av[132];
__device__ __nv_bfloat16 g_wp [1605632];      // packed split weights
__device__ __nv_bfloat16 g_hp [NN * 2 * H];   // packed split h
__device__ __nv_bfloat16 g_ffp[NN * 4 * H];   // packed split ff mid (K=512)
__device__ __nv_bfloat16 g_nfp[NN * 128];     // packed split node_feats (K=64)

// ---------------------------------------------------------------------------
// Helpers
// ---------------------------------------------------------------------------
__device__ __forceinline__ float wredsum(float v) {
    #pragma unroll
    for (int o = 16; o > 0; o >>= 1) v += __shfl_xor_sync(0xffffffffu, v, o);
    return v;
}

__device__ __forceinline__ void bf16split(float x, __nv_bfloat16& hi, __nv_bfloat16& lo) {
    hi = __float2bfloat16(x);
    lo = __float2bfloat16(x - __bfloat162float(hi));
}

// ---------------------------------------------------------------------------
// Weight preprocessing: transpose [K,N]->[N,K], split, pack per-32 chunk
// ---------------------------------------------------------------------------
struct WDesc { const float* src; int K; int N; int off; };
struct WTab  { WDesc w[11]; };

__global__ __launch_bounds__(256) void prep_kernel(WTab tab, int total) {
    int idx = blockIdx.x * 256 + threadIdx.x;
    if (idx >= total) return;
    int acc = 0;
    #pragma unroll
    for (int i = 0; i < 11; i++) {
        int K = tab.w[i].K, Nn = tab.w[i].N;
        int sz = K * Nn;
        if (idx < acc + sz) {
            int r = idx - acc;            // src-linear: r = k*N + n
            int k = r / Nn, n = r % Nn;
            __nv_bfloat16 hi, lo;
            bf16split(tab.w[i].src[r], hi, lo);
            int d = tab.w[i].off + n * 2 * K + (k >> 5) * 64 + (k & 31);
            g_wp[d]      = hi;
            g_wp[d + 32] = lo;
            return;
        }
        acc += sz;
    }
}

// node_feats fp32 -> packed split (K=64, row stride 128)
__global__ __launch_bounds__(256) void nfsplit_kernel(const float* __restrict__ nf) {
    int i = blockIdx.x * 256 + threadIdx.x;     // i = m*64 + k
    int m = i >> 6, k = i & 63;
    __nv_bfloat16 hi, lo;
    bf16split(nf[i], hi, lo);
    int d = m * 128 + (k >> 5) * 64 + (k & 31);
    g_nfp[d]      = hi;
    g_nfp[d + 32] = lo;
}

// ---------------------------------------------------------------------------
// bf16-split tensor-core GEMM, register-staged double buffer.
// Interleaved SMEM tiles: one tile per operand, row = [hi x32 | lo x32],
// row stride 72 elems (144B -> conflict-free LDSM phases; STS = row copy).
// C[16384 x ndim] = A[16384 x KDIM] @ W (+bias)(+act)
// EPI: 0 none, 1 gelu, 2 relu.  OUTM: bit0 = fp32 C, bit1 = packed split C.
// ---------------------------------------------------------------------------
constexpr int LKI = 72;                       // interleaved row stride (elems)
constexpr int TILE_I = 128 * LKI;             // 9216 elems per operand tile
constexpr int STAGE_E = 2 * TILE_I;           // A tile + B tile
constexpr int GEMM_SMEM_BYTES = 2 * STAGE_E * 2;  // 73728 B

template<int KDIM, int EPI, int OUTM>
__global__ __launch_bounds__(256) void tgemm(const __nv_bfloat16* __restrict__ Ap,
                                             const __nv_bfloat16* __restrict__ Bp,
                                             const float* __restrict__ bias,
                                             float* __restrict__ Cf,
                                             __nv_bfloat16* __restrict__ Cpk,
                                             int ndim) {
    extern __shared__ char smem_raw[];
    __nv_bfloat16* sb = (__nv_bfloat16*)smem_raw;
    __shared__ float s_bias[128];

    const int tid = threadIdx.x, wid = tid >> 5;
    const int bm = blockIdx.y * 128, bn = blockIdx.x * 128;
    const int m0 = (wid & 3) * 32, n0 = (wid >> 2) * 64;

    if (tid < 128) s_bias[tid] = bias ? bias[bn + tid] : 0.f;

    // staging map: 8 threads per row-chunk (128B), 4 row-iterations per operand
    const int r0 = tid >> 3;                  // 0..31
    const int kc = (tid & 7) * 8;             // 0..56 within packed 64-group
    constexpr int RS = 2 * KDIM;              // packed row stride (elems)

    uint4 rg[8];
    auto ldg = [&](int c) {
        const __nv_bfloat16* gA = Ap + (size_t)(bm + r0) * RS + c * 64 + kc;
        const __nv_bfloat16* gB = Bp + (size_t)(bn + r0) * RS + c * 64 + kc;
        #pragma unroll
        for (int i = 0; i < 4; i++) rg[i]     = *(const uint4*)(gA + (size_t)i * 32 * RS);
        #pragma unroll
        for (int i = 0; i < 4; i++) rg[4 + i] = *(const uint4*)(gB + (size_t)i * 32 * RS);
    };
    auto sts = [&](int s) {
        __nv_bfloat16* base = sb + s * STAGE_E;
        #pragma unroll
        for (int i = 0; i < 4; i++)
            *(uint4*)(base + (r0 + i * 32) * LKI + kc) = rg[i];
        #pragma unroll
        for (int i = 0; i < 4; i++)
            *(uint4*)(base + TILE_I + (r0 + i * 32) * LKI + kc) = rg[4 + i];
    };

    wmma::fragment<wmma::accumulator, 16, 16, 16, float> acc[2][4];
    #pragma unroll
    for (int m = 0; m < 2; m++)
        #pragma unroll
        for (int n = 0; n < 4; n++) wmma::fill_fragment(acc[m][n], 0.f);

    constexpr int NC = KDIM / 32;
    ldg(0); sts(0);
    __syncthreads();

    for (int c = 0; c < NC; c++) {
        if (c + 1 < NC) ldg(c + 1);
        const __nv_bfloat16* At = sb + (c & 1) * STAGE_E;
        const __nv_bfloat16* Bt = At + TILE_I;
        #pragma unroll
        for (int k2 = 0; k2 < 2; k2++) {
            const int kk = k2 * 16;
            wmma::fragment<wmma::matrix_a, 16, 16, 16, __nv_bfloat16, wmma::row_major> ah0, ah1, al0, al1;
            wmma::load_matrix_sync(ah0, At + (m0     ) * LKI + kk, LKI);
            wmma::load_matrix_sync(ah1, At + (m0 + 16) * LKI + kk, LKI);
            wmma::load_matrix_sync(al0, At + (m0     ) * LKI + 32 + kk, LKI);
            wmma::load_matrix_sync(al1, At + (m0 + 16) * LKI + 32 + kk, LKI);
            #pragma unroll
            for (int nn = 0; nn < 4; nn++) {
                wmma::fragment<wmma::matrix_b, 16, 16, 16, __nv_bfloat16, wmma::col_major> bh, bl;
                wmma::load_matrix_sync(bh, Bt + (n0 + nn * 16) * LKI + kk, LKI);
                wmma::load_matrix_sync(bl, Bt + (n0 + nn * 16) * LKI + 32 + kk, LKI);
                wmma::mma_sync(acc[0][nn], ah0, bh, acc[0][nn]);
                wmma::mma_sync(acc[1][nn], ah1, bh, acc[1][nn]);
                wmma::mma_sync(acc[0][nn], ah0, bl, acc[0][nn]);
                wmma::mma_sync(acc[1][nn], ah1, bl, acc[1][nn]);
                wmma::mma_sync(acc[0][nn], al0, bh, acc[0][nn]);
                wmma::mma_sync(acc[1][nn], al1, bh, acc[1][nn]);
            }
        }
        if (c + 1 < NC) sts((c + 1) & 1);
        __syncthreads();
    }

    // epilogue: stage through SMEM, apply bias/act, coalesced stores
    float* Cs = (float*)smem_raw;                 // [128][132]
    #pragma unroll
    for (int m = 0; m < 2; m++)
        #pragma unroll
        for (int n = 0; n < 4; n++)
            wmma::store_matrix_sync(Cs + (m0 + m * 16) * 132 + n0 + n * 16,
                                    acc[m][n], 132, wmma::mem_row_major);
    __syncthreads();

    #pragma unroll
    for (int i = 0; i < 16; i++) {
        int idx4 = tid + i * 256;
        int r = idx4 >> 5, c4 = (idx4 & 31) * 4;
        float4 v = *(float4*)(Cs + r * 132 + c4);
        v.x += s_bias[c4 + 0]; v.y += s_bias[c4 + 1];
        v.z += s_bias[c4 + 2]; v.w += s_bias[c4 + 3];
        if (EPI == 1) {
            v.x = 0.5f * v.x * (1.f + erff(v.x * 0.70710678118654752f));
            v.y = 0.5f * v.y * (1.f + erff(v.y * 0.70710678118654752f));
            v.z = 0.5f * v.z * (1.f + erff(v.z * 0.70710678118654752f));
            v.w = 0.5f * v.w * (1.f + erff(v.w * 0.70710678118654752f));
        } else if (EPI == 2) {
            v.x = fmaxf(v.x, 0.f); v.y = fmaxf(v.y, 0.f);
            v.z = fmaxf(v.z, 0.f); v.w = fmaxf(v.w, 0.f);
        }
        if (OUTM & 1) {
            size_t o = (size_t)(bm + r) * ndim + bn + c4;
            *(float4*)(Cf + o) = v;
        }
        if (OUTM & 2) {
            int gc = bn + c4;
            size_t pb = (size_t)(bm + r) * 2 * ndim + (size_t)(gc >> 5) * 64 + (gc & 31);
            __nv_bfloat16 h4[4], l4[4];
            bf16split(v.x, h4[0], l4[0]); bf16split(v.y, h4[1], l4[1]);
            bf16split(v.z, h4[2], l4[2]); bf16split(v.w, h4[3], l4[3]);
            *(uint2*)(Cpk + pb)      = *(uint2*)h4;
            *(uint2*)(Cpk + pb + 32) = *(uint2*)l4;
        }
    }
}

// ---------------------------------------------------------------------------
// av[l][k] = sum_j We[k,j] * gat_a[l, 2H+j] ;  bs[l] = sum_j be[j]*gat_a[l,2H+j]
// ---------------------------------------------------------------------------
__global__ void av_kernel(const float* __restrict__ We, const float* __restrict__ be,
                          const float* __restrict__ gat_a) {
    int t = threadIdx.x;
    if (t < 128) {
        int l = t >> 5, k = t & 31;
        const float* a2e = gat_a + l * 768 + 512;
        float s = 0.f;
        for (int j = 0; j < H; j++) s += We[k * H + j] * a2e[j];
        g_av[t] = s;
    } else if (t < 132) {
        int l = t - 128;
        const float* a2e = gat_a + l * 768 + 512;
        float s = 0.f;
        for (int j = 0; j < H; j++) s += be[j] * a2e[j];
        g_av[128 + l] = s;
    }
}

__global__ __launch_bounds__(256) void edot_kernel(const float* __restrict__ ef) {
    __shared__ float sav[132];
    int t = threadIdx.x;
    if (t < 132) sav[t] = g_av[t];
    __syncthreads();
    int e = blockIdx.x * 256 + t;
    float f[32];
    const float4* p = (const float4*)(ef + (size_t)e * 32);
    #pragma unroll
    for (int i = 0; i < 8; i++) {
        float4 v = p[i];
        f[4*i] = v.x; f[4*i+1] = v.y; f[4*i+2] = v.z; f[4*i+3] = v.w;
    }
    #pragma unroll
    for (int l = 0; l < LG; l++) {
        float s = sav[128 + l];
        #pragma unroll
        for (int k = 0; k < 32; k++) s += f[k] * sav[l * 32 + k];
        g_edot[l * EE + e] = s;
    }
}

// ---------------------------------------------------------------------------
// GAT layer (per-graph CTA), residual+LN in place into g_h (+ packed split)
// ---------------------------------------------------------------------------
__global__ __launch_bounds__(256) void gat_kernel(int l,
                                                  const float* __restrict__ gat_a,
                                                  const float* __restrict__ gat_lng,
                                                  const float* __restrict__ gat_lnb,
                                                  const int* __restrict__ dst) {
    extern __shared__ float sm[];
    float* ms = sm;
    float* s1 = sm + NPG * H;
    float* s2 = s1 + NPG;
    const int b = blockIdx.x, tid = threadIdx.x;
    const int w = tid >> 5, lane = tid & 31;

    const float* msrc = g_m + (size_t)b * NPG * H;
    for (int i = tid * 4; i < NPG * H; i += 1024)
        *(float4*)(ms + i) = *(const float4*)(msrc + i);
    __syncthreads();

    const float* a1 = gat_a + l * 768;
    const float* a2 = a1 + H;
    for (int q = 0; q < 8; q++) {
        int nl = w * 8 + q;
        float p1 = 0.f, p2 = 0.f;
        #pragma unroll
        for (int j = 0; j < 8; j++) {
            int d = lane + 32 * j;
            float v = ms[nl * H + d];
            p1 += v * a1[d];
            p2 += v * a2[d];
        }
        p1 = wredsum(p1);
        p2 = wredsum(p2);
        if (lane == 0) { s1[nl] = p1; s2[nl] = p2; }
    }
    __syncthreads();

    const float* ed  = g_edot + (size_t)l * EE;
    const float* lgg = gat_lng + l * H;
    const float* lgb = gat_lnb + l * H;

    for (int q = 0; q < 8; q++) {
        int nl = w * 8 + q;
        int n  = b * NPG + nl;
        int eb = n * DEG;
        float s1v = s1[nl];
        float lgt[8]; int di[8];
        float mx = -1e30f;
        #pragma unroll
        for (int k = 0; k < 8; k++) {
            di[k] = dst[eb + k] - b * NPG;
            float t = s1v + s2[di[k]] + ed[eb + k];
            t = (t >= 0.f) ? t : 0.01f * t;
            lgt[k] = t;
            mx = fmaxf(mx, t);
        }
        float den = 0.f;
        #pragma unroll
        for (int k = 0; k < 8; k++) { lgt[k] = expf(lgt[k] - mx); den += lgt[k]; }
        float inv = 1.f / den;
        #pragma unroll
        for (int k = 0; k < 8; k++) lgt[k] *= inv;

        float r[8]; float ssum = 0.f;
        #pragma unroll
        for (int j = 0; j < 8; j++) {
            int d = lane + 32 * j;
            float acc = 0.f;
            #pragma unroll
            for (int k = 0; k < 8; k++) acc += lgt[k] * ms[di[k] * H + d];
            acc += g_h[(size_t)n * H + d];
            r[j] = acc; ssum += acc;
        }
        ssum = wredsum(ssum);
        float mean = ssum * (1.f / H);
        float vv = 0.f;
        #pragma unroll
        for (int j = 0; j < 8; j++) { float t = r[j] - mean; vv += t * t; }
        vv = wredsum(vv);
        float rstd = rsqrtf(vv * (1.f / H) + 1e-5f);
        #pragma unroll
        for (int j = 0; j < 8; j++) {
            int d = lane + 32 * j;
            float o = (r[j] - mean) * rstd * lgg[d] + lgb[d];
            g_h[(size_t)n * H + d] = o;
            __nv_bfloat16 hh, hl;
            bf16split(o, hh, hl);
            size_t pb = (size_t)n * 512 + j * 64 + lane;   // packed: chunk j, elem lane
            g_hp[pb]      = hh;
            g_hp[pb + 32] = hl;
        }
    }
}

// ---------------------------------------------------------------------------
// Fused global attention + residual LayerNorm: one CTA per graph.
// Accumulates o[64][256] in SMEM across 8 heads, then LN(o + h) -> g_h, g_hp.
// ---------------------------------------------------------------------------
constexpr int ATT_SMEM_BYTES = (3 * 64 * 33 + 64 * 257 + 8 * 64) * 4;  // 93,824 B

__global__ __launch_bounds__(256) void attnln_kernel(const float* __restrict__ g,
                                                     const float* __restrict__ bt) {
    extern __shared__ float as_[];
    float* qs = as_;                  // [64][33]
    float* ks = qs + 64 * 33;
    float* vs = ks + 64 * 33;
    float* os = vs + 64 * 33;         // [64][257]
    float* ps = os + 64 * 257;        // [8][64]
    const int b = blockIdx.x, tid = threadIdx.x;
    const int w = tid >> 5, lane = tid & 31;

    for (int hd = 0; hd < 8; hd++) {
        __syncthreads();
        for (int i = tid; i < 2048; i += 256) {
            int r = i >> 5, c = i & 31;
            size_t off = (size_t)(b * NPG + r) * 768 + hd * 32 + c;
            qs[r * 33 + c] = g_qkv[off];
            ks[r * 33 + c] = g_qkv[off + 256];
            vs[r * 33 + c] = g_qkv[off + 512];
        }
        __syncthreads();
        for (int q8 = 0; q8 < 8; q8++) {
            int i = w * 8 + q8;
            float s0 = 0.f, s1 = 0.f;
            #pragma unroll
            for (int d = 0; d < 32; d++) {
                float qd = qs[i * 33 + d];
                s0 += qd * ks[lane * 33 + d];
                s1 += qd * ks[(lane + 32) * 33 + d];
            }
            s0 *= 0.17677669529663687f;
            s1 *= 0.17677669529663687f;
            float mx = fmaxf(s0, s1);
            #pragma unroll
            for (int o = 16; o > 0; o >>= 1) mx = fmaxf(mx, __shfl_xor_sync(0xffffffffu, mx, o));
            float e0 = expf(s0 - mx), e1 = expf(s1 - mx);
            float sme = wredsum(e0 + e1);
            float inv = 1.f / sme;
            ps[w * 64 + lane]      = e0 * inv;
            ps[w * 64 + lane + 32] = e1 * inv;
            __syncwarp();
            float o = 0.f;
            #pragma unroll
            for (int j = 0; j < 64; j++) o += ps[w * 64 + j] * vs[j * 33 + lane];
            os[i * 257 + hd * 32 + lane] = o;
            __syncwarp();
        }
    }
    __syncthreads();

    // residual + LN (identical op order to resln_kernel)
    for (int q = 0; q < 8; q++) {
        int nl = w * 8 + q;
        int n  = b * NPG + nl;
        float r[8]; float s = 0.f;
        #pragma unroll
        for (int j = 0; j < 8; j++) {
            int d = lane + 32 * j;
            float v = g_h[(size_t)n * H + d] + os[nl * 257 + d];
            r[j] = v; s += v;
        }
        s = wredsum(s);
        float mean = s * (1.f / H);
        float vv = 0.f;
        #pragma unroll
        for (int j = 0; j < 8; j++) { float t = r[j] - mean; vv += t * t; }
        vv = wredsum(vv);
        float rstd = rsqrtf(vv * (1.f / H) + 1e-6f);
        #pragma unroll
        for (int j = 0; j < 8; j++) {
            int d = lane + 32 * j;
            float o = (r[j] - mean) * rstd * g[d] + bt[d];
            g_h[(size_t)n * H + d] = o;
            __nv_bfloat16 hh, hl;
            bf16split(o, hh, hl);
            size_t pb = (size_t)n * 512 + j * 64 + lane;
            g_hp[pb]      = hh;
            g_hp[pb + 32] = hl;
        }
    }
}

// ---------------------------------------------------------------------------
// x = LayerNorm(x + y), y=g_m, x=g_h  (+ packed split of result)
// ---------------------------------------------------------------------------
__global__ __launch_bounds__(256) void resln_kernel(const float* __restrict__ g,
                                                    const float* __restrict__ bt,
                                                    float eps) {
    const int w = threadIdx.x >> 5, lane = threadIdx.x & 31;
    const int n = blockIdx.x * 8 + w;
    float r[8]; float s = 0.f;
    #pragma unroll
    for (int j = 0; j < 8; j++) {
        int d = lane + 32 * j;
        float v = g_h[(size_t)n * H + d] + g_m[(size_t)n * H + d];
        r[j] = v; s += v;
    }
    s = wredsum(s);
    float mean = s * (1.f / H);
    float vv = 0.f;
    #pragma unroll
    for (int j = 0; j < 8; j++) { float t = r[j] - mean; vv += t * t; }
    vv = wredsum(vv);
    float rstd = rsqrtf(vv * (1.f / H) + eps);
    #pragma unroll
    for (int j = 0; j < 8; j++) {
        int d = lane + 32 * j;
        float o = (r[j] - mean) * rstd * g[d] + bt[d];
        g_h[(size_t)n * H + d] = o;
        __nv_bfloat16 hh, hl;
        bf16split(o, hh, hl);
        size_t pb = (size_t)n * 512 + j * 64 + lane;
        g_hp[pb]      = hh;
        g_hp[pb + 32] = hl;
    }
}

// ---------------------------------------------------------------------------
// Fused gating + readout: one CTA per graph.
// sc[n] = relu_out[n] . gW2 + gb2 (relu_out in g_m); softmax over 64;
// out[b] = sum_n softmax_n * h[n]
// ---------------------------------------------------------------------------
__global__ __launch_bounds__(256) void readout_kernel(const float* __restrict__ gW2,
                                                      const float* __restrict__ gb2,
                                                      float* __restrict__ out) {
    const int b = blockIdx.x, tid = threadIdx.x;
    const int w = tid >> 5, lane = tid & 31;
    __shared__ float sg[64], pe[64];

    for (int q = 0; q < 8; q++) {
        int nl = w * 8 + q;
        int n  = b * NPG + nl;
        float s = 0.f;
        #pragma unroll
        for (int j = 0; j < 8; j++) {
            int d = lane + 32 * j;
            s += g_m[(size_t)n * H + d] * gW2[d];
        }
        s = wredsum(s);
        if (lane == 0) sg[nl] = s + gb2[0];
    }
    __syncthreads();
    if (tid < 64) {
        float mx = -1e30f;
        for (int n = 0; n < 64; n++) mx = fmaxf(mx, sg[n]);
        float se = 0.f;
        for (int n = 0; n < 64; n++) se += expf(sg[n] - mx);
        pe[tid] = expf(sg[tid] - mx) / se;
    }
    __syncthreads();
    float acc = 0.f;
    for (int n = 0; n < 64; n++)
        acc += pe[n] * g_h[(size_t)(b * NPG + n) * H + tid];
    out[b * H + tid] = acc;
}

// ---------------------------------------------------------------------------
// Launch
// ---------------------------------------------------------------------------
extern "C" void kernel_launch(void* const* d_in, const int* in_sizes, int n_in,
                              void* d_out, int out_size) {
    const float* node_feats = (const float*)d_in[0];
    const float* edge_feats = (const float*)d_in[1];
    const int*   dst        = (const int*)  d_in[3];
    const float* Wn      = (const float*)d_in[4];
    const float* bn      = (const float*)d_in[5];
    const float* We      = (const float*)d_in[6];
    const float* be      = (const float*)d_in[7];
    const float* gat_W   = (const float*)d_in[8];
    const float* gat_a   = (const float*)d_in[9];
    const float* gat_lng = (const float*)d_in[10];
    const float* gat_lnb = (const float*)d_in[11];
    const float* Wq      = (const float*)d_in[12];
    const float* Wk      = (const float*)d_in[13];
    const float* Wv      = (const float*)d_in[14];
    const float* att_lng = (const float*)d_in[15];
    const float* att_lnb = (const float*)d_in[16];
    const float* ff_W1   = (const float*)d_in[17];
    const float* ff_b1   = (const float*)d_in[18];
    const float* ff_W2   = (const float*)d_in[19];
    const float* ff_b2   = (const float*)d_in[20];
    const float* ff_lng  = (const float*)d_in[21];
    const float* ff_lnb  = (const float*)d_in[22];
    const float* gW1     = (const float*)d_in[23];
    const float* gb1     = (const float*)d_in[24];
    const float* gW2     = (const float*)d_in[25];
    const float* gb2     = (const float*)d_in[26];
    float* out = (float*)d_out;

    float *ph, *pm, *pqkv;
    __nv_bfloat16 *pw, *php, *pffp, *pnfp;
    cudaGetSymbolAddress((void**)&ph,   g_h);
    cudaGetSymbolAddress((void**)&pm,   g_m);
    cudaGetSymbolAddress((void**)&pqkv, g_qkv);
    cudaGetSymbolAddress((void**)&pw,   g_wp);
    cudaGetSymbolAddress((void**)&php,  g_hp);
    cudaGetSymbolAddress((void**)&pffp, g_ffp);
    cudaGetSymbolAddress((void**)&pnfp, g_nfp);

    // packed weight offsets (elems, each weight = 2*K*N)
    const int O_WN  = 0;
    const int O_G0  = 32768;
    const int O_G1  = 163840;
    const int O_G2  = 294912;
    const int O_G3  = 425984;
    const int O_QKV = 557056;
    const int O_F1  = 950272;
    const int O_F2  = 1212416;
    const int O_GW  = 1474560;
    WTab tab;
    tab.w[0]  = { Wn,              64,  256, O_WN };
    tab.w[1]  = { gat_W + 0*65536, 256, 256, O_G0 };
    tab.w[2]  = { gat_W + 1*65536, 256, 256, O_G1 };
    tab.w[3]  = { gat_W + 2*65536, 256, 256, O_G2 };
    tab.w[4]  = { gat_W + 3*65536, 256, 256, O_G3 };
    tab.w[5]  = { Wq,              256, 256, O_QKV };
    tab.w[6]  = { Wk,              256, 256, O_QKV + 131072 };
    tab.w[7]  = { Wv,              256, 256, O_QKV + 262144 };
    tab.w[8]  = { ff_W1,           256, 512, O_F1 };
    tab.w[9]  = { ff_W2,           512, 256, O_F2 };
    tab.w[10] = { gW1,             256, 256, O_GW };
    const int TOTAL_W = 802816;

    cudaFuncSetAttribute(tgemm<64, 0, 3>,  cudaFuncAttributeMaxDynamicSharedMemorySize, GEMM_SMEM_BYTES);
    cudaFuncSetAttribute(tgemm<256, 0, 1>, cudaFuncAttributeMaxDynamicSharedMemorySize, GEMM_SMEM_BYTES);
    cudaFuncSetAttribute(tgemm<256, 1, 2>, cudaFuncAttributeMaxDynamicSharedMemorySize, GEMM_SMEM_BYTES);
    cudaFuncSetAttribute(tgemm<512, 0, 1>, cudaFuncAttributeMaxDynamicSharedMemorySize, GEMM_SMEM_BYTES);
    cudaFuncSetAttribute(tgemm<256, 2, 1>, cudaFuncAttributeMaxDynamicSharedMemorySize, GEMM_SMEM_BYTES);
    const int GAT_SMEM = (NPG * H + 128) * (int)sizeof(float);
    cudaFuncSetAttribute(gat_kernel, cudaFuncAttributeMaxDynamicSharedMemorySize, GAT_SMEM);
    cudaFuncSetAttribute(attnln_kernel, cudaFuncAttributeMaxDynamicSharedMemorySize, ATT_SMEM_BYTES);

    // preprocess: weights, node_feats split, edge scalars
    prep_kernel<<<(TOTAL_W + 255) / 256, 256>>>(tab, TOTAL_W);
    nfsplit_kernel<<<NN * 64 / 256, 256>>>(node_feats);
    av_kernel<<<1, 160>>>(We, be, gat_a);
    edot_kernel<<<EE / 256, 256>>>(edge_feats);

    // h = node_feats @ Wn + bn   (writes fp32 h + packed split)
    tgemm<64, 0, 3><<<dim3(2, 128), 256, GEMM_SMEM_BYTES>>>(
        pnfp, pw + O_WN, bn, ph, php, 256);

    // GAT stack
    const int OG[4] = { O_G0, O_G1, O_G2, O_G3 };
    for (int l = 0; l < LG; l++) {
        tgemm<256, 0, 1><<<dim3(2, 128), 256, GEMM_SMEM_BYTES>>>(
            php, pw + OG[l], nullptr, pm, nullptr, 256);
        gat_kernel<<<BG, 256, GAT_SMEM>>>(l, gat_a, gat_lng, gat_lnb, dst);
    }

    // global attention (fused QKV) + fused residual LN
    tgemm<256, 0, 1><<<dim3(6, 128), 256, GEMM_SMEM_BYTES>>>(
        php, pw + O_QKV, nullptr, pqkv, nullptr, 768);
    attnln_kernel<<<BG, 256, ATT_SMEM_BYTES>>>(att_lng, att_lnb);

    // feed-forward
    tgemm<256, 1, 2><<<dim3(4, 128), 256, GEMM_SMEM_BYTES>>>(
        php, pw + O_F1, ff_b1, nullptr, pffp, 512);
    tgemm<512, 0, 1><<<dim3(2, 128), 256, GEMM_SMEM_BYTES>>>(
        pffp, pw + O_F2, ff_b2, pm, nullptr, 256);
    resln_kernel<<<NN / 8, 256>>>(ff_lng, ff_lnb, 1e-6f);

    // gated readout (gsc fused into readout)
    tgemm<256, 2, 1><<<dim3(2, 128), 256, GEMM_SMEM_BYTES>>>(
        php, pw + O_GW, gb1, pm, nullptr, 256);
    readout_kernel<<<BG, 256>>>(gW2, gb2, out);
}